// round 16
// baseline (speedup 1.0000x reference)
#include <cuda_runtime.h>
#include <cstdint>

#define NU 100000
#define NI 50000
#define NN 150000
#define NNZ_E 4800000
#define DIM 64
#define EPS_F 0.1f
#define SCAN_NB 147

// ---------------- static device scratch (allocation-free rule) ----------------
// Zero-initialized at module load; every launch restores the invariants it
// relies on (g_count re-zeroed by k_scan, g_flag re-zeroed by k_init).
__device__ __align__(256) float g_ego0[(size_t)NN * DIM];   // 38.4 MB
__device__ int  g_rowptr[NN + 1];
__device__ int  g_count[NN];                 // zero before k_init; re-zeroed in k_scan
__device__ int  g_flag[SCAN_NB];             // lookback flags; zeroed in k_init
__device__ __align__(16) int2 g_edges[NNZ_E];               // 38.4 MB: {col, val-bits}
__device__ __align__(8)  int  g_pack[NNZ_E];                // 19.2 MB: (row<<8)|rank

// ---------------- Threefry-2x32, 20 rounds (exact JAX semantics) ----------------
__host__ __device__ inline void tf2x32(uint32_t k0, uint32_t k1,
                                       uint32_t x0, uint32_t x1,
                                       uint32_t& o0, uint32_t& o1) {
    uint32_t k2 = k0 ^ k1 ^ 0x1BD11BDAu;
    x0 += k0; x1 += k1;
#define TFR(r) { x0 += x1; x1 = (x1 << (r)) | (x1 >> (32 - (r))); x1 ^= x0; }
    TFR(13) TFR(15) TFR(26) TFR(6)   x0 += k1; x1 += k2 + 1u;
    TFR(17) TFR(29) TFR(16) TFR(24)  x0 += k2; x1 += k0 + 2u;
    TFR(13) TFR(15) TFR(26) TFR(6)   x0 += k0; x1 += k1 + 3u;
    TFR(17) TFR(29) TFR(16) TFR(24)  x0 += k1; x1 += k2 + 4u;
    TFR(13) TFR(15) TFR(26) TFR(6)   x0 += k2; x1 += k0 + 5u;
#undef TFR
    o0 = x0; o1 = x1;
}

__device__ __forceinline__ float u01f(uint32_t b) {
    return __uint_as_float((b >> 9) | 0x3f800000u) - 1.0f;
}

__device__ __forceinline__ float sgnf(float v) {
    return (v > 0.f) ? 1.f : ((v < 0.f) ? -1.f : 0.f);
}

// ---------------- kernel 1: histogram + packed rank memo + concat + flags ------
// grid: 9375 x 256 = 2.4M threads; 2 edges each; one float4 concat element each.
// Rank fits in 8 bits (Poisson(32) degrees; max observed rank ~80).
__global__ void k_init(const int2* __restrict__ rows2,
                       const float4* __restrict__ u, const float4* __restrict__ it) {
    int t = blockIdx.x * blockDim.x + threadIdx.x;          // [0, 2.4M)
    if (blockIdx.x == 0 && threadIdx.x < SCAN_NB) g_flag[threadIdx.x] = 0;
    int2 rr = __ldcs(&rows2[t]);                            // streaming, read-once
    int r0 = atomicAdd(&g_count[rr.x], 1);                  // rank within row
    int r1 = atomicAdd(&g_count[rr.y], 1);
    __stcs(&reinterpret_cast<int2*>(g_pack)[t],
           make_int2((rr.x << 8) | r0, (rr.y << 8) | r1));  // coalesced memo
    const int NU4 = NU * DIM / 4;                           // 1.6M
    float4 v = (t < NU4) ? __ldcs(&u[t]) : __ldcs(&it[t - NU4]);
    reinterpret_cast<float4*>(g_ego0)[t] = v;
}

// ---------------- kernel 2: single-pass scan (decoupled lookback) ----------------
__global__ void __launch_bounds__(1024) k_scan() {
    __shared__ int sh[1024];
    __shared__ int sh_exc;
    int gid = blockIdx.x * 1024 + threadIdx.x;
    int v = 0;
    if (gid < NN) { v = g_count[gid]; g_count[gid] = 0; }   // restore invariant
    sh[threadIdx.x] = v;
    __syncthreads();
#pragma unroll
    for (int off = 1; off < 1024; off <<= 1) {
        int t = (threadIdx.x >= off) ? sh[threadIdx.x - off] : 0;
        __syncthreads();
        sh[threadIdx.x] += t;
        __syncthreads();
    }
    int total = sh[1023];                                   // block aggregate
    if (threadIdx.x < 32) {
        int lane = threadIdx.x;
        if (lane == 0)
            atomicExch(&g_flag[blockIdx.x], (total << 2) | 1);
        int exc = 0;
        int p = (int)blockIdx.x - 1;
        while (p >= 0) {                                    // warp-parallel lookback
            int idx = p - lane;
            int f = 0;
            if (idx >= 0) {
                do { f = *(volatile int*)&g_flag[idx]; } while ((f & 3) == 0);
            }
            unsigned inc = __ballot_sync(0xffffffffu, idx >= 0 && (f & 3) == 2);
            int stop = inc ? (__ffs(inc) - 1) : 32;
            int c = (idx >= 0 && lane <= stop) ? (f >> 2) : 0;
#pragma unroll
            for (int o = 16; o; o >>= 1) c += __shfl_xor_sync(0xffffffffu, c, o);
            exc += c;
            if (inc) break;
            p -= 32;
        }
        if (lane == 0) {
            atomicExch(&g_flag[blockIdx.x], ((exc + total) << 2) | 2);
            sh_exc = exc;
        }
    }
    __syncthreads();
    int base = sh_exc;
    if (gid < NN) g_rowptr[gid] = base + sh[threadIdx.x] - v;   // exclusive
    if (blockIdx.x == SCAN_NB - 1 && threadIdx.x == 1023)
        g_rowptr[NN] = base + total;
}

// ---------------- kernel 3: atomic-free counting-sort scatter (1 edge/thread) ----
__global__ void k_scatter(const int* __restrict__ cols,
                          const float* __restrict__ vals) {
    int i = blockIdx.x * blockDim.x + threadIdx.x;          // grid covers NNZ_E
    int pk = __ldcs(&g_pack[i]);                            // (row<<8)|rank, read-once
    int p = g_rowptr[pk >> 8] + (pk & 255);                 // rowptr L2-hot (600KB)
    int   c = __ldcs(&cols[i]);                             // streaming
    float v = __ldcs(&vals[i]);
    g_edges[p] = make_int2(c, __float_as_int(v));           // consumed by hops: keep
}

// ---------------- kernels 4-6: fused SpMM gather + threefry noise ----------------
// R10-exact hop: one warp per row, row order preserved; lane covers dims
// (2*lane, 2*lane+1); noise (pure ALU, free under gather latency) before the
// loop; single xin base pointer resolved ONCE in device code; sequential
// single-edge FMA accumulation. Do NOT restructure the loop body.
// Edge loads are evict-first (__ldcs): read once per hop, so they must not
// displace the high-reuse ego rows (each re-read ~32x per hop).
// 64-thread blocks: finest drain granularity under Poisson row-length imbalance.
// phase 0: xin = g_ego0     -> write layer_out           (e1, also hop-1 input)
// phase 1: xin = layer_out  -> write g_ego0              (e2)
// phase 2: xin = g_ego0     -> mean_out = (layer + ego0 + e3) / 3  (stcs: dead)
__global__ void __launch_bounds__(64) k_hop(int phase, uint32_t hk0, uint32_t hk1,
                                            float* __restrict__ mean_out,
                                            const float* __restrict__ layer_in,
                                            float* __restrict__ layer_out) {
    const float* __restrict__ xin = (phase == 1) ? layer_in : g_ego0;

    int w    = (blockIdx.x * blockDim.x + threadIdx.x) >> 5;   // row, grid exact
    int lane = threadIdx.x & 31;

    int s = g_rowptr[w];
    int e = g_rowptr[w + 1];

    // noise first: partitionable threefry, bits = out0 ^ out1 of block (0, idx)
    uint32_t idx = (uint32_t)w * DIM + 2u * (uint32_t)lane;
    uint32_t a0, a1, b0, b1;
    tf2x32(hk0, hk1, 0u, idx,      a0, a1);
    tf2x32(hk0, hk1, 0u, idx + 1u, b0, b1);
    float u0 = u01f(a0 ^ a1);
    float u1 = u01f(b0 ^ b1);

    float ss = fmaf(u0, u0, u1 * u1);
#pragma unroll
    for (int off = 16; off; off >>= 1)
        ss += __shfl_xor_sync(0xffffffffu, ss, off);
    float f = EPS_F * rsqrtf(ss);

    float acc0 = 0.f, acc1 = 0.f;
#pragma unroll 4
    for (int j = s; j < e; j++) {
        int2 cv = __ldcs(&g_edges[j]);                          // uniform, evict-first
        const float2 xv = *reinterpret_cast<const float2*>(
            xin + (size_t)cv.x * DIM + 2 * lane);
        float v = __int_as_float(cv.y);
        acc0 = fmaf(v, xv.x, acc0);
        acc1 = fmaf(v, xv.y, acc1);
    }

    float e0 = acc0 + sgnf(acc0) * u0 * f;
    float e1 = acc1 + sgnf(acc1) * u1 * f;

    size_t p = (size_t)w * DIM + 2 * lane;
    float2 ev = make_float2(e0, e1);
    if (phase == 0) {
        *reinterpret_cast<float2*>(layer_out + p) = ev;         // re-read by hop1
    } else if (phase == 1) {
        *reinterpret_cast<float2*>(g_ego0 + p)    = ev;         // re-read by hop2
    } else {
        float2 lv  = *reinterpret_cast<const float2*>(layer_in + p);
        float2 e2v = *reinterpret_cast<const float2*>(g_ego0 + p);
        float2 m;
        m.x = (lv.x + e2v.x + ev.x) * (1.f / 3.f);
        m.y = (lv.y + e2v.y + ev.y) * (1.f / 3.f);
        __stcs(reinterpret_cast<float2*>(mean_out + p), m);     // dead after write
    }
}

// ---------------- launch ----------------
extern "C" void kernel_launch(void* const* d_in, const int* in_sizes, int n_in,
                              void* d_out, int out_size) {
    const float* user = (const float*)d_in[0];
    const float* item = (const float*)d_in[1];
    const int*   rows = (const int*)d_in[2];
    const int*   cols = (const int*)d_in[3];
    const float* vals = (const float*)d_in[4];
    float* out = (float*)d_out;
    float* mean_out  = out;                       // user_all ++ item_all
    float* layer_out = out + (size_t)NN * DIM;    // user_layer ++ item_layer

    // per-hop keys: fold_in(key(42), k) == threefry((0,42),(0,k))
    uint32_t hk0[3], hk1[3];
    for (int k = 0; k < 3; k++)
        tf2x32(0u, 42u, 0u, (uint32_t)k, hk0[k], hk1[k]);

    k_init<<<9375, 256>>>((const int2*)rows, (const float4*)user, (const float4*)item);
    k_scan<<<SCAN_NB, 1024>>>();
    k_scatter<<<NNZ_E / 256, 256>>>(cols, vals);

    // 150000 warps (1 row each) = 75000 blocks x 64; hop0 is launch #4 (profiled)
    k_hop<<<75000, 64>>>(0, hk0[0], hk1[0], mean_out, layer_out, layer_out);
    k_hop<<<75000, 64>>>(1, hk0[1], hk1[1], mean_out, layer_out, layer_out);
    k_hop<<<75000, 64>>>(2, hk0[2], hk1[2], mean_out, layer_out, layer_out);
}

// round 17
// speedup vs baseline: 1.0288x; 1.0288x over previous
#include <cuda_runtime.h>
#include <cstdint>

#define NU 100000
#define NI 50000
#define NN 150000
#define NNZ_E 4800000
#define DIM 64
#define EPS_F 0.1f
#define SCAN_NB 147

// ---------------- static device scratch (allocation-free rule) ----------------
// Zero-initialized at module load; every launch restores the invariants it
// relies on (g_count re-zeroed by k_scan, g_flag re-zeroed by k_init).
__device__ __align__(256) float g_ego0[(size_t)NN * DIM];   // 38.4 MB
__device__ int  g_rowptr[NN + 1];
__device__ int  g_count[NN];                 // zero before k_init; re-zeroed in k_scan
__device__ int  g_flag[SCAN_NB];             // lookback flags; zeroed in k_init
__device__ __align__(16) int2 g_edges[NNZ_E];               // 38.4 MB: {col, val-bits}
__device__ __align__(8)  int  g_pack[NNZ_E];                // 19.2 MB: (row<<8)|rank

// ---------------- Threefry-2x32, 20 rounds (exact JAX semantics) ----------------
__host__ __device__ inline void tf2x32(uint32_t k0, uint32_t k1,
                                       uint32_t x0, uint32_t x1,
                                       uint32_t& o0, uint32_t& o1) {
    uint32_t k2 = k0 ^ k1 ^ 0x1BD11BDAu;
    x0 += k0; x1 += k1;
#define TFR(r) { x0 += x1; x1 = (x1 << (r)) | (x1 >> (32 - (r))); x1 ^= x0; }
    TFR(13) TFR(15) TFR(26) TFR(6)   x0 += k1; x1 += k2 + 1u;
    TFR(17) TFR(29) TFR(16) TFR(24)  x0 += k2; x1 += k0 + 2u;
    TFR(13) TFR(15) TFR(26) TFR(6)   x0 += k0; x1 += k1 + 3u;
    TFR(17) TFR(29) TFR(16) TFR(24)  x0 += k1; x1 += k2 + 4u;
    TFR(13) TFR(15) TFR(26) TFR(6)   x0 += k2; x1 += k0 + 5u;
#undef TFR
    o0 = x0; o1 = x1;
}

__device__ __forceinline__ float u01f(uint32_t b) {
    return __uint_as_float((b >> 9) | 0x3f800000u) - 1.0f;
}

__device__ __forceinline__ float sgnf(float v) {
    return (v > 0.f) ? 1.f : ((v < 0.f) ? -1.f : 0.f);
}

// ---------------- kernel 1: histogram + packed rank memo + concat + flags ------
// grid: 9375 x 256 = 2.4M threads; 2 edges each; one float4 concat element each.
// Rank fits in 8 bits (Poisson(32) degrees; max observed rank ~80).
__global__ void k_init(const int2* __restrict__ rows2,
                       const float4* __restrict__ u, const float4* __restrict__ it) {
    int t = blockIdx.x * blockDim.x + threadIdx.x;          // [0, 2.4M)
    if (blockIdx.x == 0 && threadIdx.x < SCAN_NB) g_flag[threadIdx.x] = 0;
    int2 rr = rows2[t];                                     // edges 2t, 2t+1
    int r0 = atomicAdd(&g_count[rr.x], 1);                  // rank within row
    int r1 = atomicAdd(&g_count[rr.y], 1);
    reinterpret_cast<int2*>(g_pack)[t] =
        make_int2((rr.x << 8) | r0, (rr.y << 8) | r1);      // coalesced memo
    const int NU4 = NU * DIM / 4;                           // 1.6M
    float4 v = (t < NU4) ? u[t] : it[t - NU4];
    reinterpret_cast<float4*>(g_ego0)[t] = v;
}

// ---------------- kernel 2: single-pass scan (decoupled lookback) ----------------
__global__ void __launch_bounds__(1024) k_scan() {
    __shared__ int sh[1024];
    __shared__ int sh_exc;
    int gid = blockIdx.x * 1024 + threadIdx.x;
    int v = 0;
    if (gid < NN) { v = g_count[gid]; g_count[gid] = 0; }   // restore invariant
    sh[threadIdx.x] = v;
    __syncthreads();
#pragma unroll
    for (int off = 1; off < 1024; off <<= 1) {
        int t = (threadIdx.x >= off) ? sh[threadIdx.x - off] : 0;
        __syncthreads();
        sh[threadIdx.x] += t;
        __syncthreads();
    }
    int total = sh[1023];                                   // block aggregate
    if (threadIdx.x < 32) {
        int lane = threadIdx.x;
        if (lane == 0)
            atomicExch(&g_flag[blockIdx.x], (total << 2) | 1);
        int exc = 0;
        int p = (int)blockIdx.x - 1;
        while (p >= 0) {                                    // warp-parallel lookback
            int idx = p - lane;
            int f = 0;
            if (idx >= 0) {
                do { f = *(volatile int*)&g_flag[idx]; } while ((f & 3) == 0);
            }
            unsigned inc = __ballot_sync(0xffffffffu, idx >= 0 && (f & 3) == 2);
            int stop = inc ? (__ffs(inc) - 1) : 32;
            int c = (idx >= 0 && lane <= stop) ? (f >> 2) : 0;
#pragma unroll
            for (int o = 16; o; o >>= 1) c += __shfl_xor_sync(0xffffffffu, c, o);
            exc += c;
            if (inc) break;
            p -= 32;
        }
        if (lane == 0) {
            atomicExch(&g_flag[blockIdx.x], ((exc + total) << 2) | 2);
            sh_exc = exc;
        }
    }
    __syncthreads();
    int base = sh_exc;
    if (gid < NN) g_rowptr[gid] = base + sh[threadIdx.x] - v;   // exclusive
    if (blockIdx.x == SCAN_NB - 1 && threadIdx.x == 1023)
        g_rowptr[NN] = base + total;
}

// ---------------- kernel 3: atomic-free counting-sort scatter (1 edge/thread) ----
__global__ void k_scatter(const int* __restrict__ cols,
                          const float* __restrict__ vals) {
    int i = blockIdx.x * blockDim.x + threadIdx.x;          // grid covers NNZ_E
    int pk = g_pack[i];                                     // (row<<8) | rank
    int p = g_rowptr[pk >> 8] + (pk & 255);                 // rowptr L2-hot (600KB)
    g_edges[p] = make_int2(cols[i], __float_as_int(vals[i]));
}

// ---------------- kernels 4-6: fused SpMM gather + threefry noise ----------------
// R10-exact hop (one warp per row, sequential single-edge FMA chain — the only
// shape that is both fast and numerically matched; do NOT restructure), with the
// sole change vs R15: gather-loop unroll 4 -> 8 (unrolling preserves the FP
// chain exactly; it only batches more independent LDGs per scheduling window).
// 64-thread blocks: finest drain granularity under Poisson row-length imbalance.
// phase 0: xin = g_ego0     -> write layer_out           (e1, also hop-1 input)
// phase 1: xin = layer_out  -> write g_ego0              (e2)
// phase 2: xin = g_ego0     -> mean_out = (layer + ego0 + e3) / 3
__global__ void __launch_bounds__(64) k_hop(int phase, uint32_t hk0, uint32_t hk1,
                                            float* __restrict__ mean_out,
                                            const float* __restrict__ layer_in,
                                            float* __restrict__ layer_out) {
    const float* __restrict__ xin = (phase == 1) ? layer_in : g_ego0;

    int w    = (blockIdx.x * blockDim.x + threadIdx.x) >> 5;   // row, grid exact
    int lane = threadIdx.x & 31;

    int s = g_rowptr[w];
    int e = g_rowptr[w + 1];

    // noise first: partitionable threefry, bits = out0 ^ out1 of block (0, idx)
    uint32_t idx = (uint32_t)w * DIM + 2u * (uint32_t)lane;
    uint32_t a0, a1, b0, b1;
    tf2x32(hk0, hk1, 0u, idx,      a0, a1);
    tf2x32(hk0, hk1, 0u, idx + 1u, b0, b1);
    float u0 = u01f(a0 ^ a1);
    float u1 = u01f(b0 ^ b1);

    float ss = fmaf(u0, u0, u1 * u1);
#pragma unroll
    for (int off = 16; off; off >>= 1)
        ss += __shfl_xor_sync(0xffffffffu, ss, off);
    float f = EPS_F * rsqrtf(ss);

    float acc0 = 0.f, acc1 = 0.f;
#pragma unroll 8
    for (int j = s; j < e; j++) {
        int2 cv = g_edges[j];                                   // uniform broadcast
        const float2 xv = *reinterpret_cast<const float2*>(
            xin + (size_t)cv.x * DIM + 2 * lane);
        float v = __int_as_float(cv.y);
        acc0 = fmaf(v, xv.x, acc0);
        acc1 = fmaf(v, xv.y, acc1);
    }

    float e0 = acc0 + sgnf(acc0) * u0 * f;
    float e1 = acc1 + sgnf(acc1) * u1 * f;

    size_t p = (size_t)w * DIM + 2 * lane;
    float2 ev = make_float2(e0, e1);
    if (phase == 0) {
        *reinterpret_cast<float2*>(layer_out + p) = ev;
    } else if (phase == 1) {
        *reinterpret_cast<float2*>(g_ego0 + p)    = ev;
    } else {
        float2 lv  = *reinterpret_cast<const float2*>(layer_in + p);
        float2 e2v = *reinterpret_cast<const float2*>(g_ego0 + p);
        float2 m;
        m.x = (lv.x + e2v.x + ev.x) * (1.f / 3.f);
        m.y = (lv.y + e2v.y + ev.y) * (1.f / 3.f);
        *reinterpret_cast<float2*>(mean_out + p) = m;
    }
}

// ---------------- launch ----------------
extern "C" void kernel_launch(void* const* d_in, const int* in_sizes, int n_in,
                              void* d_out, int out_size) {
    const float* user = (const float*)d_in[0];
    const float* item = (const float*)d_in[1];
    const int*   rows = (const int*)d_in[2];
    const int*   cols = (const int*)d_in[3];
    const float* vals = (const float*)d_in[4];
    float* out = (float*)d_out;
    float* mean_out  = out;                       // user_all ++ item_all
    float* layer_out = out + (size_t)NN * DIM;    // user_layer ++ item_layer

    // per-hop keys: fold_in(key(42), k) == threefry((0,42),(0,k))
    uint32_t hk0[3], hk1[3];
    for (int k = 0; k < 3; k++)
        tf2x32(0u, 42u, 0u, (uint32_t)k, hk0[k], hk1[k]);

    k_init<<<9375, 256>>>((const int2*)rows, (const float4*)user, (const float4*)item);
    k_scan<<<SCAN_NB, 1024>>>();
    k_scatter<<<NNZ_E / 256, 256>>>(cols, vals);

    // 150000 warps (1 row each) = 75000 blocks x 64; hop0 is launch #4 (profiled)
    k_hop<<<75000, 64>>>(0, hk0[0], hk1[0], mean_out, layer_out, layer_out);
    k_hop<<<75000, 64>>>(1, hk0[1], hk1[1], mean_out, layer_out, layer_out);
    k_hop<<<75000, 64>>>(2, hk0[2], hk1[2], mean_out, layer_out, layer_out);
}